// round 5
// baseline (speedup 1.0000x reference)
#include <cuda_runtime.h>
#include <cuda_bf16.h>
#include <cstdint>
#include <math.h>

#define N_NODES 50000
#define H 256
#define E_EDGES 800000
#define EPS_LN 1e-5f
#define EPS_BN 1e-5f

// ---------------- scratch (device globals; no allocation allowed) -------------
__device__ float g_x[(size_t)N_NODES * H];            // layer activations (pre-BN for l>0)
__device__ float g_xw[(size_t)N_NODES * H];           // x @ W (fp32, GEMM out / gather src)
__device__ __nv_bfloat16 g_wth[3][H * H];             // W^T hi: [n][k]
__device__ __nv_bfloat16 g_wtl[3][H * H];             // W^T lo: [n][k]
__device__ int   g_deg[N_NODES];
__device__ float g_dinv[N_NODES];
__device__ int   g_off[N_NODES + 1];
__device__ int   g_cur[N_NODES];
__device__ int   g_csrc[E_EDGES];
__device__ float g_sum[H];
__device__ float g_sumsq[H];
__device__ float g_scale[H];
__device__ float g_shift[H];

// ---------------- degree / CSR build ----------------
__global__ void k_zero_deg() {
    int i = blockIdx.x * blockDim.x + threadIdx.x;
    if (i < N_NODES) g_deg[i] = 0;
}

__global__ void k_count(const int* __restrict__ dst) {
    int e = blockIdx.x * blockDim.x + threadIdx.x;
    if (e < E_EDGES) atomicAdd(&g_deg[dst[e]], 1);
}

__global__ void k_scan() {
    __shared__ int swarp[32];
    __shared__ int s_carry;
    int tid = threadIdx.x, lane = tid & 31, wid = tid >> 5;
    if (tid == 0) s_carry = 0;
    __syncthreads();
    for (int base = 0; base < N_NODES; base += 1024) {
        int i = base + tid;
        int v = (i < N_NODES) ? g_deg[i] : 0;
        int x = v;
        #pragma unroll
        for (int o = 1; o < 32; o <<= 1) {
            int t = __shfl_up_sync(0xffffffffu, x, o);
            if (lane >= o) x += t;
        }
        if (lane == 31) swarp[wid] = x;
        __syncthreads();
        if (wid == 0) {
            int y = swarp[lane];
            #pragma unroll
            for (int o = 1; o < 32; o <<= 1) {
                int t = __shfl_up_sync(0xffffffffu, y, o);
                if (lane >= o) y += t;
            }
            swarp[lane] = y;
        }
        __syncthreads();
        int incl = x + (wid ? swarp[wid - 1] : 0);
        int carry = s_carry;
        if (i < N_NODES) {
            int o = carry + incl - v;
            g_off[i] = o;
            g_cur[i] = o;
            g_dinv[i] = rsqrtf((float)v + 1.0f);
        }
        __syncthreads();
        if (tid == 1023) s_carry = carry + incl;
        __syncthreads();
    }
    if (threadIdx.x == 0) g_off[N_NODES] = s_carry;
}

__global__ void k_fill(const int* __restrict__ src, const int* __restrict__ dst) {
    int e = blockIdx.x * blockDim.x + threadIdx.x;
    if (e < E_EDGES) {
        int d = dst[e];
        int pos = atomicAdd(&g_cur[d], 1);
        g_csrc[pos] = src[e];
    }
}

// ---------------- W^T split (fp32 -> bf16 hi/lo), [n][k] layout --------------
__global__ void k_wsplit(const float* __restrict__ W,
                         __nv_bfloat16* __restrict__ hi, __nv_bfloat16* __restrict__ lo) {
    int n = blockIdx.x, k = threadIdx.x;
    float w = W[k * H + n];
    __nv_bfloat16 h = __float2bfloat16(w);
    hi[n * H + k] = h;
    lo[n * H + k] = __float2bfloat16(w - __bfloat162float(h));
}

// ---------------- input proj + LayerNorm + ELU -> fp32 g_x -------------------
__global__ void k_input(const float* __restrict__ ctrl,
                        const float* __restrict__ w_in, const float* __restrict__ b_in,
                        const float* __restrict__ ln_g, const float* __restrict__ ln_b) {
    int gwarp = (blockIdx.x * blockDim.x + threadIdx.x) >> 5;
    int lane = threadIdx.x & 31;
    if (gwarp >= N_NODES) return;
    float c = ctrl[gwarp];
    float v[8];
    float s = 0.f, s2 = 0.f;
    #pragma unroll
    for (int j = 0; j < 8; j++) {
        int ch = lane * 8 + j;
        float t = fmaf(c, w_in[ch], b_in[ch]);
        v[j] = t; s += t; s2 += t * t;
    }
    #pragma unroll
    for (int o = 16; o; o >>= 1) {
        s  += __shfl_xor_sync(0xffffffffu, s, o);
        s2 += __shfl_xor_sync(0xffffffffu, s2, o);
    }
    float mu = s * (1.0f / H);
    float var = fmaxf(s2 * (1.0f / H) - mu * mu, 0.f);
    float r = rsqrtf(var + EPS_LN);
    float* out = g_x + (size_t)gwarp * H + lane * 8;
    float y[8];
    #pragma unroll
    for (int j = 0; j < 8; j++) {
        int ch = lane * 8 + j;
        float t = fmaf((v[j] - mu) * r, ln_g[ch], ln_b[ch]);
        y[j] = (t > 0.f) ? t : expm1f(t);
    }
    *(float4*)(out)     = make_float4(y[0], y[1], y[2], y[3]);
    *(float4*)(out + 4) = make_float4(y[4], y[5], y[6], y[7]);
}

// ---------------- mma.sync bf16 GEMM with fused BN+ELU+split on A-load -------
// g_xw = elu(bn(g_x)) @ (Wh+Wl). CTA 128x128, 8 warps, BK=32.
#define ASTRIDE 40   // bf16 elems per smem row (80 B)

__device__ __forceinline__ void mma16816(float* c, const uint32_t* a, const uint32_t* b) {
    asm volatile("mma.sync.aligned.m16n8k16.row.col.f32.bf16.bf16.f32 "
                 "{%0,%1,%2,%3}, {%4,%5,%6,%7}, {%8,%9}, {%0,%1,%2,%3};"
                 : "+f"(c[0]), "+f"(c[1]), "+f"(c[2]), "+f"(c[3])
                 : "r"(a[0]), "r"(a[1]), "r"(a[2]), "r"(a[3]), "r"(b[0]), "r"(b[1]));
}

__global__ __launch_bounds__(256, 2) void k_gemm_mma(const __nv_bfloat16* __restrict__ Bh,
                                                     const __nv_bfloat16* __restrict__ Bl,
                                                     int do_bn) {
    __shared__ __nv_bfloat16 sAh[128 * ASTRIDE];
    __shared__ __nv_bfloat16 sAl[128 * ASTRIDE];
    __shared__ __nv_bfloat16 sBh[128 * ASTRIDE];
    __shared__ __nv_bfloat16 sBl[128 * ASTRIDE];

    int tid = threadIdx.x, wid = tid >> 5, lane = tid & 31;
    int g = lane >> 2, tg = lane & 3;
    int bm = blockIdx.y * 128, bn = blockIdx.x * 128;
    int wm = (wid & 3) * 32, wn = (wid >> 2) * 64;

    float c[2][8][4] = {};

    int arow = tid >> 1;        // 0..127
    int ahalf = tid & 1;        // which 16-elem half of the 32-k chunk
    int gr = bm + arow;
    bool a_ok = (gr < N_NODES);
    const float* pA = g_x + (size_t)(a_ok ? gr : 0) * H;
    int af4 = ahalf * 2;
    const float4* pBh = (const float4*)(Bh + (size_t)(bn + arow) * H);
    const float4* pBl = (const float4*)(Bl + (size_t)(bn + arow) * H);

    for (int kc = 0; kc < 8; kc++) {
        // ---- A: load 16 fp32, (BN+ELU), split hi/lo, store to smem
        int c0 = kc * 32 + ahalf * 16;
        float v[16];
        if (a_ok) {
            *(float4*)(v)      = *(const float4*)(pA + c0);
            *(float4*)(v + 4)  = *(const float4*)(pA + c0 + 4);
            *(float4*)(v + 8)  = *(const float4*)(pA + c0 + 8);
            *(float4*)(v + 12) = *(const float4*)(pA + c0 + 12);
        } else {
            #pragma unroll
            for (int j = 0; j < 16; j++) v[j] = 0.f;
        }
        __nv_bfloat16 hi[16], lo[16];
        if (do_bn) {
            #pragma unroll
            for (int j = 0; j < 16; j++) {
                float y = fmaf(v[j], g_scale[c0 + j], g_shift[c0 + j]);
                y = (y > 0.f) ? y : expm1f(y);
                __nv_bfloat16 h = __float2bfloat16(y);
                hi[j] = h; lo[j] = __float2bfloat16(y - __bfloat162float(h));
            }
        } else {
            #pragma unroll
            for (int j = 0; j < 16; j++) {
                __nv_bfloat16 h = __float2bfloat16(v[j]);
                hi[j] = h; lo[j] = __float2bfloat16(v[j] - __bfloat162float(h));
            }
        }
        int so = arow * ASTRIDE + ahalf * 16;   // bf16 elem index, 16B aligned (80B rows)
        *(float4*)&sAh[so]     = *(float4*)&hi[0];
        *(float4*)&sAh[so + 8] = *(float4*)&hi[8];
        *(float4*)&sAl[so]     = *(float4*)&lo[0];
        *(float4*)&sAl[so + 8] = *(float4*)&lo[8];

        // ---- B: weights (pre-split bf16), rows bn..bn+127, k cols kc*32..+31
        int ko = kc * 4;
        *(float4*)&sBh[so]     = pBh[ko + af4];
        *(float4*)&sBh[so + 8] = pBh[ko + af4 + 1];
        *(float4*)&sBl[so]     = pBl[ko + af4];
        *(float4*)&sBl[so + 8] = pBl[ko + af4 + 1];
        __syncthreads();

        // ---- compute
        #pragma unroll
        for (int k16 = 0; k16 < 2; k16++) {
            int kb = k16 * 32;  // byte offset of k16 block (16 bf16)
            uint32_t ah[2][4], al[2][4];
            #pragma unroll
            for (int mt = 0; mt < 2; mt++) {
                int r = wm + mt * 16 + g;
                int o = r * (ASTRIDE * 2) + kb + tg * 4;
                ah[mt][0] = *(const uint32_t*)((const char*)sAh + o);
                ah[mt][1] = *(const uint32_t*)((const char*)sAh + o + 8 * ASTRIDE * 2);
                ah[mt][2] = *(const uint32_t*)((const char*)sAh + o + 16);
                ah[mt][3] = *(const uint32_t*)((const char*)sAh + o + 8 * ASTRIDE * 2 + 16);
                al[mt][0] = *(const uint32_t*)((const char*)sAl + o);
                al[mt][1] = *(const uint32_t*)((const char*)sAl + o + 8 * ASTRIDE * 2);
                al[mt][2] = *(const uint32_t*)((const char*)sAl + o + 16);
                al[mt][3] = *(const uint32_t*)((const char*)sAl + o + 8 * ASTRIDE * 2 + 16);
            }
            #pragma unroll
            for (int nt = 0; nt < 8; nt++) {
                int rb = wn + nt * 8 + g;
                int o = rb * (ASTRIDE * 2) + kb + tg * 4;
                uint32_t bh[2], bl[2];
                bh[0] = *(const uint32_t*)((const char*)sBh + o);
                bh[1] = *(const uint32_t*)((const char*)sBh + o + 16);
                bl[0] = *(const uint32_t*)((const char*)sBl + o);
                bl[1] = *(const uint32_t*)((const char*)sBl + o + 16);
                #pragma unroll
                for (int mt = 0; mt < 2; mt++) {
                    mma16816(c[mt][nt], ah[mt], bh);
                    mma16816(c[mt][nt], ah[mt], bl);
                    mma16816(c[mt][nt], al[mt], bh);
                }
            }
        }
        __syncthreads();
    }

    // ---- epilogue: fp32 out
    #pragma unroll
    for (int mt = 0; mt < 2; mt++) {
        int r0 = bm + wm + mt * 16 + g;
        #pragma unroll
        for (int nt = 0; nt < 8; nt++) {
            int col = bn + wn + nt * 8 + tg * 2;
            if (r0 < N_NODES)
                *(float2*)&g_xw[(size_t)r0 * H + col] = make_float2(c[mt][nt][0], c[mt][nt][1]);
            if (r0 + 8 < N_NODES)
                *(float2*)&g_xw[(size_t)(r0 + 8) * H + col] = make_float2(c[mt][nt][2], c[mt][nt][3]);
        }
    }
}

// ---------------- zero BN accumulators ----------------
__global__ void k_zero_stats() {
    int t = threadIdx.x;
    g_sum[t] = 0.f;
    g_sumsq[t] = 0.f;
}

// ---------------- CSR aggregation (fp32 gather, 2-edge unroll) + BN stats ----
__global__ __launch_bounds__(256) void k_aggregate() {
    __shared__ float s_sum[H];
    __shared__ float s_sq[H];
    int tid = threadIdx.x;
    s_sum[tid] = 0.f;
    s_sq[tid] = 0.f;
    __syncthreads();

    int node = blockIdx.x * 8 + (tid >> 5);
    int lane = tid & 31;

    float dn = g_dinv[node];
    const float4* row = (const float4*)(g_xw + (size_t)node * H);
    float4 a0 = row[lane];
    float4 a1 = row[32 + lane];
    float w = dn * dn;
    float4 acc0 = make_float4(a0.x * w, a0.y * w, a0.z * w, a0.w * w);
    float4 acc1 = make_float4(a1.x * w, a1.y * w, a1.z * w, a1.w * w);

    int beg = g_off[node], end = g_off[node + 1];
    int j = beg;
    for (; j + 1 < end; j += 2) {
        int s0 = g_csrc[j];
        int s1 = g_csrc[j + 1];
        float cf0 = g_dinv[s0] * dn;
        float cf1 = g_dinv[s1] * dn;
        const float4* r0 = (const float4*)(g_xw + (size_t)s0 * H);
        const float4* r1 = (const float4*)(g_xw + (size_t)s1 * H);
        float4 b0 = r0[lane];
        float4 b1 = r0[32 + lane];
        float4 b2 = r1[lane];
        float4 b3 = r1[32 + lane];
        acc0.x = fmaf(cf0, b0.x, acc0.x); acc0.y = fmaf(cf0, b0.y, acc0.y);
        acc0.z = fmaf(cf0, b0.z, acc0.z); acc0.w = fmaf(cf0, b0.w, acc0.w);
        acc1.x = fmaf(cf0, b1.x, acc1.x); acc1.y = fmaf(cf0, b1.y, acc1.y);
        acc1.z = fmaf(cf0, b1.z, acc1.z); acc1.w = fmaf(cf0, b1.w, acc1.w);
        acc0.x = fmaf(cf1, b2.x, acc0.x); acc0.y = fmaf(cf1, b2.y, acc0.y);
        acc0.z = fmaf(cf1, b2.z, acc0.z); acc0.w = fmaf(cf1, b2.w, acc0.w);
        acc1.x = fmaf(cf1, b3.x, acc1.x); acc1.y = fmaf(cf1, b3.y, acc1.y);
        acc1.z = fmaf(cf1, b3.z, acc1.z); acc1.w = fmaf(cf1, b3.w, acc1.w);
    }
    if (j < end) {
        int s0 = g_csrc[j];
        float cf0 = g_dinv[s0] * dn;
        const float4* r0 = (const float4*)(g_xw + (size_t)s0 * H);
        float4 b0 = r0[lane];
        float4 b1 = r0[32 + lane];
        acc0.x = fmaf(cf0, b0.x, acc0.x); acc0.y = fmaf(cf0, b0.y, acc0.y);
        acc0.z = fmaf(cf0, b0.z, acc0.z); acc0.w = fmaf(cf0, b0.w, acc0.w);
        acc1.x = fmaf(cf0, b1.x, acc1.x); acc1.y = fmaf(cf0, b1.y, acc1.y);
        acc1.z = fmaf(cf0, b1.z, acc1.z); acc1.w = fmaf(cf0, b1.w, acc1.w);
    }

    float4* out = (float4*)(g_x + (size_t)node * H);
    out[lane] = acc0;
    out[32 + lane] = acc1;

    int c0 = lane * 4, c1 = 128 + lane * 4;
    atomicAdd(&s_sum[c0 + 0], acc0.x); atomicAdd(&s_sq[c0 + 0], acc0.x * acc0.x);
    atomicAdd(&s_sum[c0 + 1], acc0.y); atomicAdd(&s_sq[c0 + 1], acc0.y * acc0.y);
    atomicAdd(&s_sum[c0 + 2], acc0.z); atomicAdd(&s_sq[c0 + 2], acc0.z * acc0.z);
    atomicAdd(&s_sum[c0 + 3], acc0.w); atomicAdd(&s_sq[c0 + 3], acc0.w * acc0.w);
    atomicAdd(&s_sum[c1 + 0], acc1.x); atomicAdd(&s_sq[c1 + 0], acc1.x * acc1.x);
    atomicAdd(&s_sum[c1 + 1], acc1.y); atomicAdd(&s_sq[c1 + 1], acc1.y * acc1.y);
    atomicAdd(&s_sum[c1 + 2], acc1.z); atomicAdd(&s_sq[c1 + 2], acc1.z * acc1.z);
    atomicAdd(&s_sum[c1 + 3], acc1.w); atomicAdd(&s_sq[c1 + 3], acc1.w * acc1.w);

    __syncthreads();
    atomicAdd(&g_sum[tid], s_sum[tid]);
    atomicAdd(&g_sumsq[tid], s_sq[tid]);
}

// ---------------- BN finalize ----------------
__global__ void k_bn_finalize(const float* __restrict__ gamma,
                              const float* __restrict__ beta) {
    int t = threadIdx.x;
    float mean = g_sum[t] * (1.0f / N_NODES);
    float var = fmaxf(g_sumsq[t] * (1.0f / N_NODES) - mean * mean, 0.f);
    float r = rsqrtf(var + EPS_BN);
    float sc = r * gamma[t];
    g_scale[t] = sc;
    g_shift[t] = beta[t] - mean * sc;
}

// ---------------- head: BN3 + ELU + dot ----------------
__global__ void k_head(const float* __restrict__ w_head,
                       const float* __restrict__ b_head,
                       float* __restrict__ out) {
    int gwarp = (blockIdx.x * blockDim.x + threadIdx.x) >> 5;
    int lane = threadIdx.x & 31;
    if (gwarp >= N_NODES) return;
    const float* row = g_x + (size_t)gwarp * H + lane * 8;
    float v[8];
    *(float4*)(v)     = *(const float4*)(row);
    *(float4*)(v + 4) = *(const float4*)(row + 4);
    float s = 0.f;
    #pragma unroll
    for (int j = 0; j < 8; j++) {
        int ch = lane * 8 + j;
        float y = fmaf(v[j], g_scale[ch], g_shift[ch]);
        y = (y > 0.f) ? y : expm1f(y);
        s = fmaf(y, w_head[ch], s);
    }
    #pragma unroll
    for (int o = 16; o; o >>= 1) s += __shfl_xor_sync(0xffffffffu, s, o);
    if (lane == 0) out[gwarp] = s + b_head[0];
}

// ---------------- launch ----------------
extern "C" void kernel_launch(void* const* d_in, const int* in_sizes, int n_in,
                              void* d_out, int out_size) {
    const float* ctrl   = (const float*)d_in[0];
    const int*   eidx   = (const int*)d_in[1];
    const float* w_in   = (const float*)d_in[2];
    const float* b_in   = (const float*)d_in[3];
    const float* ln_g   = (const float*)d_in[4];
    const float* ln_b   = (const float*)d_in[5];
    const float* W[3]   = { (const float*)d_in[6],  (const float*)d_in[10], (const float*)d_in[14] };
    const float* gam[3] = { (const float*)d_in[8],  (const float*)d_in[12], (const float*)d_in[16] };
    const float* bet[3] = { (const float*)d_in[9],  (const float*)d_in[13], (const float*)d_in[17] };
    const float* w_head = (const float*)d_in[18];
    const float* b_head = (const float*)d_in[19];
    float* out = (float*)d_out;

    const int* src = eidx;
    const int* dst = eidx + E_EDGES;

    // graph structure
    k_zero_deg<<<(N_NODES + 255) / 256, 256>>>();
    k_count<<<E_EDGES / 256, 256>>>(dst);
    k_scan<<<1, 1024>>>();
    k_fill<<<E_EDGES / 256, 256>>>(src, dst);

    // weight split (W^T -> bf16 hi/lo)
    __nv_bfloat16* wh;  __nv_bfloat16* wl;
    cudaGetSymbolAddress((void**)&wh, g_wth);
    cudaGetSymbolAddress((void**)&wl, g_wtl);
    for (int l = 0; l < 3; l++)
        k_wsplit<<<H, H>>>(W[l], wh + (size_t)l * H * H, wl + (size_t)l * H * H);

    // input proj + LN + ELU -> g_x fp32
    k_input<<<N_NODES / 8, 256>>>(ctrl, w_in, b_in, ln_g, ln_b);

    dim3 gemm_grid(H / 128, (N_NODES + 127) / 128);
    for (int l = 0; l < 3; l++) {
        k_gemm_mma<<<gemm_grid, 256>>>(wh + (size_t)l * H * H, wl + (size_t)l * H * H, l > 0);
        k_zero_stats<<<1, H>>>();
        k_aggregate<<<N_NODES / 8, 256>>>();
        k_bn_finalize<<<1, H>>>(gam[l], bet[l]);
    }

    k_head<<<N_NODES / 8, 256>>>(w_head, b_head, out);
}

// round 6
// speedup vs baseline: 1.1135x; 1.1135x over previous
#include <cuda_runtime.h>
#include <cuda_bf16.h>
#include <cstdint>
#include <math.h>

#define N_NODES 50000
#define H 256
#define E_EDGES 800000
#define EPS_LN 1e-5f
#define EPS_BN 1e-5f
#define NBLK_SCAN 49   // ceil(50000/1024)

// ---------------- scratch (device globals; no allocation allowed) -------------
__device__ float g_x[(size_t)N_NODES * H];            // layer activations (pre-BN for l>0)
__device__ float g_xw[(size_t)N_NODES * H];           // x @ W (fp32, GEMM out / gather src)
__device__ __nv_bfloat16 g_wth[3][H * H];             // W^T hi: [n][k]
__device__ __nv_bfloat16 g_wtl[3][H * H];             // W^T lo: [n][k]
__device__ int   g_deg[N_NODES];
__device__ float g_dinv[N_NODES];
__device__ int   g_off[N_NODES + 1];
__device__ int   g_cur[N_NODES];
__device__ int   g_csrc[E_EDGES];
__device__ int   g_part[64];
__device__ int   g_ctr;
__device__ float g_sum[H];
__device__ float g_sumsq[H];
__device__ float g_scale[H];
__device__ float g_shift[H];

// ---------------- degree / CSR build ----------------
__global__ void k_zero_deg() {
    int i = blockIdx.x * blockDim.x + threadIdx.x;
    if (i < N_NODES) g_deg[i] = 0;
}

__global__ void k_count(const int* __restrict__ dst) {
    int e = blockIdx.x * blockDim.x + threadIdx.x;
    if (e < E_EDGES) atomicAdd(&g_deg[dst[e]], 1);
}

// phase 1: per-block sums of degrees
__global__ void k_scan_reduce() {
    __shared__ int sw[32];
    int tid = threadIdx.x, lane = tid & 31, wid = tid >> 5;
    int i = blockIdx.x * 1024 + tid;
    int v = (i < N_NODES) ? g_deg[i] : 0;
    #pragma unroll
    for (int o = 16; o; o >>= 1) v += __shfl_xor_sync(0xffffffffu, v, o);
    if (lane == 0) sw[wid] = v;
    __syncthreads();
    if (wid == 0) {
        int t = sw[lane];
        #pragma unroll
        for (int o = 16; o; o >>= 1) t += __shfl_xor_sync(0xffffffffu, t, o);
        if (lane == 0) g_part[blockIdx.x] = t;
    }
}

// phase 2: serial scan of 49 block sums (tiny)
__global__ void k_scan_offsets() {
    if (threadIdx.x == 0) {
        int run = 0;
        for (int b = 0; b < NBLK_SCAN; b++) {
            int t = g_part[b];
            g_part[b] = run;
            run += t;
        }
        g_off[N_NODES] = run;
    }
}

// phase 3: per-block exclusive scan + base offset; write off/cur/dinv
__global__ void k_scan_write() {
    __shared__ int sw[32];
    int tid = threadIdx.x, lane = tid & 31, wid = tid >> 5;
    int i = blockIdx.x * 1024 + tid;
    int v = (i < N_NODES) ? g_deg[i] : 0;
    int x = v;
    #pragma unroll
    for (int o = 1; o < 32; o <<= 1) {
        int t = __shfl_up_sync(0xffffffffu, x, o);
        if (lane >= o) x += t;
    }
    if (lane == 31) sw[wid] = x;
    __syncthreads();
    if (wid == 0) {
        int y = sw[lane];
        #pragma unroll
        for (int o = 1; o < 32; o <<= 1) {
            int t = __shfl_up_sync(0xffffffffu, y, o);
            if (lane >= o) y += t;
        }
        sw[lane] = y;
    }
    __syncthreads();
    if (i < N_NODES) {
        int excl = x - v + (wid ? sw[wid - 1] : 0) + g_part[blockIdx.x];
        g_off[i] = excl;
        g_cur[i] = excl;
        g_dinv[i] = rsqrtf((float)v + 1.0f);
    }
}

__global__ void k_fill(const int* __restrict__ src, const int* __restrict__ dst) {
    int e = blockIdx.x * blockDim.x + threadIdx.x;
    if (e < E_EDGES) {
        int d = dst[e];
        int pos = atomicAdd(&g_cur[d], 1);
        g_csrc[pos] = src[e];
    }
}

// ---------------- W^T split (fp32 -> bf16 hi/lo), [n][k] layout --------------
__global__ void k_wsplit(const float* __restrict__ W,
                         __nv_bfloat16* __restrict__ hi, __nv_bfloat16* __restrict__ lo) {
    int n = blockIdx.x, k = threadIdx.x;
    float w = W[k * H + n];
    __nv_bfloat16 h = __float2bfloat16(w);
    hi[n * H + k] = h;
    lo[n * H + k] = __float2bfloat16(w - __bfloat162float(h));
}

// ---------------- input proj + LayerNorm + ELU -> fp32 g_x -------------------
__global__ void k_input(const float* __restrict__ ctrl,
                        const float* __restrict__ w_in, const float* __restrict__ b_in,
                        const float* __restrict__ ln_g, const float* __restrict__ ln_b) {
    int gwarp = (blockIdx.x * blockDim.x + threadIdx.x) >> 5;
    int lane = threadIdx.x & 31;
    if (gwarp >= N_NODES) return;
    float c = ctrl[gwarp];
    float v[8];
    float s = 0.f, s2 = 0.f;
    #pragma unroll
    for (int j = 0; j < 8; j++) {
        int ch = lane * 8 + j;
        float t = fmaf(c, w_in[ch], b_in[ch]);
        v[j] = t; s += t; s2 += t * t;
    }
    #pragma unroll
    for (int o = 16; o; o >>= 1) {
        s  += __shfl_xor_sync(0xffffffffu, s, o);
        s2 += __shfl_xor_sync(0xffffffffu, s2, o);
    }
    float mu = s * (1.0f / H);
    float var = fmaxf(s2 * (1.0f / H) - mu * mu, 0.f);
    float r = rsqrtf(var + EPS_LN);
    float* out = g_x + (size_t)gwarp * H + lane * 8;
    float y[8];
    #pragma unroll
    for (int j = 0; j < 8; j++) {
        int ch = lane * 8 + j;
        float t = fmaf((v[j] - mu) * r, ln_g[ch], ln_b[ch]);
        y[j] = (t > 0.f) ? t : expm1f(t);
    }
    *(float4*)(out)     = make_float4(y[0], y[1], y[2], y[3]);
    *(float4*)(out + 4) = make_float4(y[4], y[5], y[6], y[7]);
}

// ---------------- mma.sync bf16 GEMM, full-width CTA 128x256, 512 threads ----
// g_xw = elu(bn(g_x)) @ (Wh+Wl). BN+ELU+split fused on A-load, done ONCE.
#define ASTRIDE 40   // bf16 elems per smem row (80 B)
#define SA_ELEMS (128 * ASTRIDE)
#define SB_ELEMS (256 * ASTRIDE)
#define GEMM_SMEM ((2 * SA_ELEMS + 2 * SB_ELEMS) * 2)

__device__ __forceinline__ void mma16816(float* c, const uint32_t* a, const uint32_t* b) {
    asm volatile("mma.sync.aligned.m16n8k16.row.col.f32.bf16.bf16.f32 "
                 "{%0,%1,%2,%3}, {%4,%5,%6,%7}, {%8,%9}, {%0,%1,%2,%3};"
                 : "+f"(c[0]), "+f"(c[1]), "+f"(c[2]), "+f"(c[3])
                 : "r"(a[0]), "r"(a[1]), "r"(a[2]), "r"(a[3]), "r"(b[0]), "r"(b[1]));
}

__global__ __launch_bounds__(512, 1) void k_gemm_mma(const __nv_bfloat16* __restrict__ Bh,
                                                     const __nv_bfloat16* __restrict__ Bl,
                                                     int do_bn) {
    extern __shared__ __nv_bfloat16 smem[];
    __nv_bfloat16* sAh = smem;
    __nv_bfloat16* sAl = smem + SA_ELEMS;
    __nv_bfloat16* sBh = smem + 2 * SA_ELEMS;
    __nv_bfloat16* sBl = smem + 2 * SA_ELEMS + SB_ELEMS;

    int tid = threadIdx.x, wid = tid >> 5, lane = tid & 31;
    int g = lane >> 2, tg = lane & 3;
    int bm = blockIdx.x * 128;
    int wm = (wid & 3) * 32, wn = (wid >> 2) * 64;

    float c[2][8][4] = {};

    // A mapping: 128 rows x 32 k, 8 fp32 per thread
    int arow = tid >> 2, aq = tid & 3;
    int gr = bm + arow;
    bool a_ok = (gr < N_NODES);
    const float* pA = g_x + (size_t)(a_ok ? gr : 0) * H;
    // B mapping: 256 rows x 32 k, 16 bf16 per thread
    int brow = tid >> 1, bhalf = tid & 1;
    const float4* pBh = (const float4*)(Bh + (size_t)brow * H);
    const float4* pBl = (const float4*)(Bl + (size_t)brow * H);

    for (int kc = 0; kc < 8; kc++) {
        // ---- A: load 8 fp32, (BN+ELU), split hi/lo, store to smem (once!)
        int c0 = kc * 32 + aq * 8;
        float v[8];
        if (a_ok) {
            *(float4*)(v)     = *(const float4*)(pA + c0);
            *(float4*)(v + 4) = *(const float4*)(pA + c0 + 4);
        } else {
            #pragma unroll
            for (int j = 0; j < 8; j++) v[j] = 0.f;
        }
        __nv_bfloat16 hi[8], lo[8];
        if (do_bn) {
            #pragma unroll
            for (int j = 0; j < 8; j++) {
                float y = fmaf(v[j], g_scale[c0 + j], g_shift[c0 + j]);
                y = (y > 0.f) ? y : expm1f(y);
                __nv_bfloat16 h = __float2bfloat16(y);
                hi[j] = h; lo[j] = __float2bfloat16(y - __bfloat162float(h));
            }
        } else {
            #pragma unroll
            for (int j = 0; j < 8; j++) {
                __nv_bfloat16 h = __float2bfloat16(v[j]);
                hi[j] = h; lo[j] = __float2bfloat16(v[j] - __bfloat162float(h));
            }
        }
        int soA = arow * ASTRIDE + aq * 8;
        *(float4*)&sAh[soA] = *(float4*)&hi[0];
        *(float4*)&sAl[soA] = *(float4*)&lo[0];

        // ---- B: pre-split bf16 weights, 16 elems per thread
        int ko = brow * 32 + kc * 4 + bhalf * 2;
        int soB = brow * ASTRIDE + bhalf * 16;
        *(float4*)&sBh[soB]     = pBh ? ((const float4*)Bh)[ko] : make_float4(0, 0, 0, 0);
        *(float4*)&sBh[soB + 8] = ((const float4*)Bh)[ko + 1];
        *(float4*)&sBl[soB]     = ((const float4*)Bl)[ko];
        *(float4*)&sBl[soB + 8] = ((const float4*)Bl)[ko + 1];
        __syncthreads();

        // ---- compute
        #pragma unroll
        for (int k16 = 0; k16 < 2; k16++) {
            int kb = k16 * 32;  // byte offset of 16-bf16 block
            uint32_t ah[2][4], al[2][4];
            #pragma unroll
            for (int mt = 0; mt < 2; mt++) {
                int r = wm + mt * 16 + g;
                int o = r * (ASTRIDE * 2) + kb + tg * 4;
                ah[mt][0] = *(const uint32_t*)((const char*)sAh + o);
                ah[mt][1] = *(const uint32_t*)((const char*)sAh + o + 8 * ASTRIDE * 2);
                ah[mt][2] = *(const uint32_t*)((const char*)sAh + o + 16);
                ah[mt][3] = *(const uint32_t*)((const char*)sAh + o + 8 * ASTRIDE * 2 + 16);
                al[mt][0] = *(const uint32_t*)((const char*)sAl + o);
                al[mt][1] = *(const uint32_t*)((const char*)sAl + o + 8 * ASTRIDE * 2);
                al[mt][2] = *(const uint32_t*)((const char*)sAl + o + 16);
                al[mt][3] = *(const uint32_t*)((const char*)sAl + o + 8 * ASTRIDE * 2 + 16);
            }
            #pragma unroll
            for (int nt = 0; nt < 8; nt++) {
                int rb = wn + nt * 8 + g;
                int o = rb * (ASTRIDE * 2) + kb + tg * 4;
                uint32_t bh[2], bl[2];
                bh[0] = *(const uint32_t*)((const char*)sBh + o);
                bh[1] = *(const uint32_t*)((const char*)sBh + o + 16);
                bl[0] = *(const uint32_t*)((const char*)sBl + o);
                bl[1] = *(const uint32_t*)((const char*)sBl + o + 16);
                #pragma unroll
                for (int mt = 0; mt < 2; mt++) {
                    mma16816(c[mt][nt], ah[mt], bh);
                    mma16816(c[mt][nt], ah[mt], bl);
                    mma16816(c[mt][nt], al[mt], bh);
                }
            }
        }
        __syncthreads();
    }

    // ---- epilogue: fp32 out
    #pragma unroll
    for (int mt = 0; mt < 2; mt++) {
        int r0 = bm + wm + mt * 16 + g;
        #pragma unroll
        for (int nt = 0; nt < 8; nt++) {
            int col = wn + nt * 8 + tg * 2;
            if (r0 < N_NODES)
                *(float2*)&g_xw[(size_t)r0 * H + col] = make_float2(c[mt][nt][0], c[mt][nt][1]);
            if (r0 + 8 < N_NODES)
                *(float2*)&g_xw[(size_t)(r0 + 8) * H + col] = make_float2(c[mt][nt][2], c[mt][nt][3]);
        }
    }
}

// ---------------- zero BN accumulators + node counter ----------------
__global__ void k_zero_stats() {
    int t = threadIdx.x;
    g_sum[t] = 0.f;
    g_sumsq[t] = 0.f;
    if (t == 0) g_ctr = 0;
}

// ---------------- CSR aggregation, dynamic load balance + BN stats -----------
__global__ __launch_bounds__(256) void k_aggregate() {
    __shared__ float s_sum[H];
    __shared__ float s_sq[H];
    int tid = threadIdx.x, lane = tid & 31;
    s_sum[tid] = 0.f;
    s_sq[tid] = 0.f;
    __syncthreads();

    for (;;) {
        int node;
        if (lane == 0) node = atomicAdd(&g_ctr, 1);
        node = __shfl_sync(0xffffffffu, node, 0);
        if (node >= N_NODES) break;

        float dn = g_dinv[node];
        const float4* row = (const float4*)(g_xw + (size_t)node * H);
        float4 a0 = row[lane];
        float4 a1 = row[32 + lane];
        float w = dn * dn;
        float4 acc0 = make_float4(a0.x * w, a0.y * w, a0.z * w, a0.w * w);
        float4 acc1 = make_float4(a1.x * w, a1.y * w, a1.z * w, a1.w * w);

        int beg = g_off[node], end = g_off[node + 1];
        int j = beg;
        for (; j + 1 < end; j += 2) {
            int s0 = g_csrc[j];
            int s1 = g_csrc[j + 1];
            float cf0 = g_dinv[s0] * dn;
            float cf1 = g_dinv[s1] * dn;
            const float4* r0 = (const float4*)(g_xw + (size_t)s0 * H);
            const float4* r1 = (const float4*)(g_xw + (size_t)s1 * H);
            float4 b0 = r0[lane];
            float4 b1 = r0[32 + lane];
            float4 b2 = r1[lane];
            float4 b3 = r1[32 + lane];
            acc0.x = fmaf(cf0, b0.x, acc0.x); acc0.y = fmaf(cf0, b0.y, acc0.y);
            acc0.z = fmaf(cf0, b0.z, acc0.z); acc0.w = fmaf(cf0, b0.w, acc0.w);
            acc1.x = fmaf(cf0, b1.x, acc1.x); acc1.y = fmaf(cf0, b1.y, acc1.y);
            acc1.z = fmaf(cf0, b1.z, acc1.z); acc1.w = fmaf(cf0, b1.w, acc1.w);
            acc0.x = fmaf(cf1, b2.x, acc0.x); acc0.y = fmaf(cf1, b2.y, acc0.y);
            acc0.z = fmaf(cf1, b2.z, acc0.z); acc0.w = fmaf(cf1, b2.w, acc0.w);
            acc1.x = fmaf(cf1, b3.x, acc1.x); acc1.y = fmaf(cf1, b3.y, acc1.y);
            acc1.z = fmaf(cf1, b3.z, acc1.z); acc1.w = fmaf(cf1, b3.w, acc1.w);
        }
        if (j < end) {
            int s0 = g_csrc[j];
            float cf0 = g_dinv[s0] * dn;
            const float4* r0 = (const float4*)(g_xw + (size_t)s0 * H);
            float4 b0 = r0[lane];
            float4 b1 = r0[32 + lane];
            acc0.x = fmaf(cf0, b0.x, acc0.x); acc0.y = fmaf(cf0, b0.y, acc0.y);
            acc0.z = fmaf(cf0, b0.z, acc0.z); acc0.w = fmaf(cf0, b0.w, acc0.w);
            acc1.x = fmaf(cf0, b1.x, acc1.x); acc1.y = fmaf(cf0, b1.y, acc1.y);
            acc1.z = fmaf(cf0, b1.z, acc1.z); acc1.w = fmaf(cf0, b1.w, acc1.w);
        }

        float4* out = (float4*)(g_x + (size_t)node * H);
        out[lane] = acc0;
        out[32 + lane] = acc1;

        int c0 = lane * 4, c1 = 128 + lane * 4;
        atomicAdd(&s_sum[c0 + 0], acc0.x); atomicAdd(&s_sq[c0 + 0], acc0.x * acc0.x);
        atomicAdd(&s_sum[c0 + 1], acc0.y); atomicAdd(&s_sq[c0 + 1], acc0.y * acc0.y);
        atomicAdd(&s_sum[c0 + 2], acc0.z); atomicAdd(&s_sq[c0 + 2], acc0.z * acc0.z);
        atomicAdd(&s_sum[c0 + 3], acc0.w); atomicAdd(&s_sq[c0 + 3], acc0.w * acc0.w);
        atomicAdd(&s_sum[c1 + 0], acc1.x); atomicAdd(&s_sq[c1 + 0], acc1.x * acc1.x);
        atomicAdd(&s_sum[c1 + 1], acc1.y); atomicAdd(&s_sq[c1 + 1], acc1.y * acc1.y);
        atomicAdd(&s_sum[c1 + 2], acc1.z); atomicAdd(&s_sq[c1 + 2], acc1.z * acc1.z);
        atomicAdd(&s_sum[c1 + 3], acc1.w); atomicAdd(&s_sq[c1 + 3], acc1.w * acc1.w);
    }

    __syncthreads();
    atomicAdd(&g_sum[tid], s_sum[tid]);
    atomicAdd(&g_sumsq[tid], s_sq[tid]);
}

// ---------------- BN finalize ----------------
__global__ void k_bn_finalize(const float* __restrict__ gamma,
                              const float* __restrict__ beta) {
    int t = threadIdx.x;
    float mean = g_sum[t] * (1.0f / N_NODES);
    float var = fmaxf(g_sumsq[t] * (1.0f / N_NODES) - mean * mean, 0.f);
    float r = rsqrtf(var + EPS_BN);
    float sc = r * gamma[t];
    g_scale[t] = sc;
    g_shift[t] = beta[t] - mean * sc;
}

// ---------------- head: BN3 + ELU + dot ----------------
__global__ void k_head(const float* __restrict__ w_head,
                       const float* __restrict__ b_head,
                       float* __restrict__ out) {
    int gwarp = (blockIdx.x * blockDim.x + threadIdx.x) >> 5;
    int lane = threadIdx.x & 31;
    if (gwarp >= N_NODES) return;
    const float* row = g_x + (size_t)gwarp * H + lane * 8;
    float v[8];
    *(float4*)(v)     = *(const float4*)(row);
    *(float4*)(v + 4) = *(const float4*)(row + 4);
    float s = 0.f;
    #pragma unroll
    for (int j = 0; j < 8; j++) {
        int ch = lane * 8 + j;
        float y = fmaf(v[j], g_scale[ch], g_shift[ch]);
        y = (y > 0.f) ? y : expm1f(y);
        s = fmaf(y, w_head[ch], s);
    }
    #pragma unroll
    for (int o = 16; o; o >>= 1) s += __shfl_xor_sync(0xffffffffu, s, o);
    if (lane == 0) out[gwarp] = s + b_head[0];
}

// ---------------- launch ----------------
extern "C" void kernel_launch(void* const* d_in, const int* in_sizes, int n_in,
                              void* d_out, int out_size) {
    const float* ctrl   = (const float*)d_in[0];
    const int*   eidx   = (const int*)d_in[1];
    const float* w_in   = (const float*)d_in[2];
    const float* b_in   = (const float*)d_in[3];
    const float* ln_g   = (const float*)d_in[4];
    const float* ln_b   = (const float*)d_in[5];
    const float* W[3]   = { (const float*)d_in[6],  (const float*)d_in[10], (const float*)d_in[14] };
    const float* gam[3] = { (const float*)d_in[8],  (const float*)d_in[12], (const float*)d_in[16] };
    const float* bet[3] = { (const float*)d_in[9],  (const float*)d_in[13], (const float*)d_in[17] };
    const float* w_head = (const float*)d_in[18];
    const float* b_head = (const float*)d_in[19];
    float* out = (float*)d_out;

    const int* src = eidx;
    const int* dst = eidx + E_EDGES;

    cudaFuncSetAttribute(k_gemm_mma, cudaFuncAttributeMaxDynamicSharedMemorySize, GEMM_SMEM);

    // graph structure
    k_zero_deg<<<(N_NODES + 255) / 256, 256>>>();
    k_count<<<E_EDGES / 256, 256>>>(dst);
    k_scan_reduce<<<NBLK_SCAN, 1024>>>();
    k_scan_offsets<<<1, 32>>>();
    k_scan_write<<<NBLK_SCAN, 1024>>>();
    k_fill<<<E_EDGES / 256, 256>>>(src, dst);

    // weight split (W^T -> bf16 hi/lo)
    __nv_bfloat16* wh;  __nv_bfloat16* wl;
    cudaGetSymbolAddress((void**)&wh, g_wth);
    cudaGetSymbolAddress((void**)&wl, g_wtl);
    for (int l = 0; l < 3; l++)
        k_wsplit<<<H, H>>>(W[l], wh + (size_t)l * H * H, wl + (size_t)l * H * H);

    // input proj + LN + ELU -> g_x fp32
    k_input<<<N_NODES / 8, 256>>>(ctrl, w_in, b_in, ln_g, ln_b);

    int gemm_grid = (N_NODES + 127) / 128;
    for (int l = 0; l < 3; l++) {
        k_gemm_mma<<<gemm_grid, 512, GEMM_SMEM>>>(wh + (size_t)l * H * H,
                                                  wl + (size_t)l * H * H, l > 0);
        k_zero_stats<<<1, H>>>();
        k_aggregate<<<592, 256>>>();
        k_bn_finalize<<<1, H>>>(gam[l], bet[l]);
    }

    k_head<<<N_NODES / 8, 256>>>(w_head, b_head, out);
}

// round 7
// speedup vs baseline: 1.2063x; 1.0833x over previous
#include <cuda_runtime.h>
#include <cuda_bf16.h>
#include <cstdint>
#include <math.h>

#define N_NODES 50000
#define H 256
#define E_EDGES 800000
#define EPS_LN 1e-5f
#define EPS_BN 1e-5f
#define NBLK_SCAN 49   // ceil(50000/1024)

// ---------------- scratch (device globals; no allocation allowed) -------------
__device__ float g_x[(size_t)N_NODES * H];            // aggregation output (pre-BN)
__device__ float g_xw[(size_t)N_NODES * H];           // x @ W (fp32, GEMM out / gather src)
__device__ __nv_bfloat16 g_wth[3][H * H];             // W^T hi: [n][k]
__device__ __nv_bfloat16 g_wtl[3][H * H];             // W^T lo: [n][k]
__device__ int   g_deg[N_NODES];
__device__ float g_dinv[N_NODES];
__device__ int   g_off[N_NODES + 1];
__device__ int   g_cur[N_NODES];
__device__ int   g_csrc[E_EDGES];
__device__ int   g_part[64];
__device__ int   g_ctr;
__device__ float g_sum[H];
__device__ float g_sumsq[H];
__device__ float g_scale[H];
__device__ float g_shift[H];
__device__ float g_lnstat[5];   // mw, mb, vw, cwb, vb

// ---------------- degree / CSR build ----------------
__global__ void k_zero_deg() {
    int i = blockIdx.x * blockDim.x + threadIdx.x;
    if (i < N_NODES) g_deg[i] = 0;
}

__global__ void k_count(const int* __restrict__ dst) {
    int e = blockIdx.x * blockDim.x + threadIdx.x;
    if (e < E_EDGES) atomicAdd(&g_deg[dst[e]], 1);
}

__global__ void k_scan_reduce() {
    __shared__ int sw[32];
    int tid = threadIdx.x, lane = tid & 31, wid = tid >> 5;
    int i = blockIdx.x * 1024 + tid;
    int v = (i < N_NODES) ? g_deg[i] : 0;
    #pragma unroll
    for (int o = 16; o; o >>= 1) v += __shfl_xor_sync(0xffffffffu, v, o);
    if (lane == 0) sw[wid] = v;
    __syncthreads();
    if (wid == 0) {
        int t = sw[lane];
        #pragma unroll
        for (int o = 16; o; o >>= 1) t += __shfl_xor_sync(0xffffffffu, t, o);
        if (lane == 0) g_part[blockIdx.x] = t;
    }
}

__global__ void k_scan_offsets() {
    if (threadIdx.x == 0) {
        int run = 0;
        for (int b = 0; b < NBLK_SCAN; b++) {
            int t = g_part[b];
            g_part[b] = run;
            run += t;
        }
        g_off[N_NODES] = run;
    }
}

__global__ void k_scan_write() {
    __shared__ int sw[32];
    int tid = threadIdx.x, lane = tid & 31, wid = tid >> 5;
    int i = blockIdx.x * 1024 + tid;
    int v = (i < N_NODES) ? g_deg[i] : 0;
    int x = v;
    #pragma unroll
    for (int o = 1; o < 32; o <<= 1) {
        int t = __shfl_up_sync(0xffffffffu, x, o);
        if (lane >= o) x += t;
    }
    if (lane == 31) sw[wid] = x;
    __syncthreads();
    if (wid == 0) {
        int y = sw[lane];
        #pragma unroll
        for (int o = 1; o < 32; o <<= 1) {
            int t = __shfl_up_sync(0xffffffffu, y, o);
            if (lane >= o) y += t;
        }
        sw[lane] = y;
    }
    __syncthreads();
    if (i < N_NODES) {
        int excl = x - v + (wid ? sw[wid - 1] : 0) + g_part[blockIdx.x];
        g_off[i] = excl;
        g_cur[i] = excl;
        g_dinv[i] = rsqrtf((float)v + 1.0f);
    }
}

__global__ void k_fill(const int* __restrict__ src, const int* __restrict__ dst) {
    int e = blockIdx.x * blockDim.x + threadIdx.x;
    if (e < E_EDGES) {
        int d = dst[e];
        int pos = atomicAdd(&g_cur[d], 1);
        g_csrc[pos] = src[e];
    }
}

// ---------------- W^T split (fp32 -> bf16 hi/lo), [n][k] layout --------------
__global__ void k_wsplit(const float* __restrict__ W,
                         __nv_bfloat16* __restrict__ hi, __nv_bfloat16* __restrict__ lo) {
    int n = blockIdx.x, k = threadIdx.x;
    float w = W[k * H + n];
    __nv_bfloat16 h = __float2bfloat16(w);
    hi[n * H + k] = h;
    lo[n * H + k] = __float2bfloat16(w - __bfloat162float(h));
}

// ---------------- input LN stats: mean/var of w_in,b_in + cov ----------------
__global__ void k_instat(const float* __restrict__ w_in, const float* __restrict__ b_in) {
    __shared__ float red[5][8];
    int t = threadIdx.x, lane = t & 31, wid = t >> 5;
    float w = w_in[t], b = b_in[t];
    float s[5] = { w, b, w * w, w * b, b * b };
    #pragma unroll
    for (int o = 16; o; o >>= 1)
        #pragma unroll
        for (int i = 0; i < 5; i++) s[i] += __shfl_xor_sync(0xffffffffu, s[i], o);
    if (lane == 0)
        #pragma unroll
        for (int i = 0; i < 5; i++) red[i][wid] = s[i];
    __syncthreads();
    if (t == 0) {
        float a[5];
        #pragma unroll
        for (int i = 0; i < 5; i++) {
            float acc = 0.f;
            for (int j = 0; j < 8; j++) acc += red[i][j];
            a[i] = acc * (1.0f / H);
        }
        g_lnstat[0] = a[0];                     // mw
        g_lnstat[1] = a[1];                     // mb
        g_lnstat[2] = a[2] - a[0] * a[0];       // vw
        g_lnstat[3] = a[3] - a[0] * a[1];       // cwb
        g_lnstat[4] = a[4] - a[1] * a[1];       // vb
    }
}

// ---------------- mma.sync bf16 GEMM, full-width CTA 128x256, 512 threads ----
// mode 0: A = elu(LN(ctrl*w_in+b_in)) computed on the fly (layer 0)
// mode 2: A = elu(bn(g_x)) via g_scale/g_shift (layers 1,2)
#define ASTRIDE 40   // bf16 elems per smem row (80 B)
#define SA_ELEMS (128 * ASTRIDE)
#define SB_ELEMS (256 * ASTRIDE)
#define GEMM_SMEM ((2 * SA_ELEMS + 2 * SB_ELEMS) * 2)

__device__ __forceinline__ void mma16816(float* c, const uint32_t* a, const uint32_t* b) {
    asm volatile("mma.sync.aligned.m16n8k16.row.col.f32.bf16.bf16.f32 "
                 "{%0,%1,%2,%3}, {%4,%5,%6,%7}, {%8,%9}, {%0,%1,%2,%3};"
                 : "+f"(c[0]), "+f"(c[1]), "+f"(c[2]), "+f"(c[3])
                 : "r"(a[0]), "r"(a[1]), "r"(a[2]), "r"(a[3]), "r"(b[0]), "r"(b[1]));
}

__global__ __launch_bounds__(512, 1) void k_gemm_mma(const __nv_bfloat16* __restrict__ Bh,
                                                     const __nv_bfloat16* __restrict__ Bl,
                                                     int mode,
                                                     const float* __restrict__ ctrl,
                                                     const float* __restrict__ w_in,
                                                     const float* __restrict__ b_in,
                                                     const float* __restrict__ ln_g,
                                                     const float* __restrict__ ln_b) {
    extern __shared__ __nv_bfloat16 smem[];
    __nv_bfloat16* sAh = smem;
    __nv_bfloat16* sAl = smem + SA_ELEMS;
    __nv_bfloat16* sBh = smem + 2 * SA_ELEMS;
    __nv_bfloat16* sBl = smem + 2 * SA_ELEMS + SB_ELEMS;

    int tid = threadIdx.x, wid = tid >> 5, lane = tid & 31;
    int g = lane >> 2, tg = lane & 3;
    int bm = blockIdx.x * 128;
    int wm = (wid & 3) * 32, wn = (wid >> 2) * 64;

    float c[2][8][4] = {};

    // A mapping: 128 rows x 32 k, 8 fp32 per thread
    int arow = tid >> 2, aq = tid & 3;
    int gr = bm + arow;
    bool a_ok = (gr < N_NODES);
    const float* pA = g_x + (size_t)(a_ok ? gr : 0) * H;
    // layer-0 closed-form LN per row
    float l0_c = 0.f, l0_mu = 0.f, l0_r = 0.f;
    if (mode == 0 && a_ok) {
        l0_c = ctrl[gr];
        l0_mu = fmaf(l0_c, g_lnstat[0], g_lnstat[1]);
        float var = fmaf(l0_c * l0_c, g_lnstat[2],
                    fmaf(2.0f * l0_c, g_lnstat[3], g_lnstat[4]));
        l0_r = rsqrtf(fmaxf(var, 0.f) + EPS_LN);
    }
    // B mapping: 256 rows x 32 k, 16 bf16 per thread
    int brow = tid >> 1, bhalf = tid & 1;

    for (int kc = 0; kc < 8; kc++) {
        // ---- A: build 8 activation values, split hi/lo, store to smem
        int c0 = kc * 32 + aq * 8;
        __nv_bfloat16 hi[8], lo[8];
        if (a_ok) {
            float y[8];
            if (mode == 0) {
                float wv[8], bv[8], gv[8], ov[8];
                *(float4*)(wv)     = *(const float4*)(w_in + c0);
                *(float4*)(wv + 4) = *(const float4*)(w_in + c0 + 4);
                *(float4*)(bv)     = *(const float4*)(b_in + c0);
                *(float4*)(bv + 4) = *(const float4*)(b_in + c0 + 4);
                *(float4*)(gv)     = *(const float4*)(ln_g + c0);
                *(float4*)(gv + 4) = *(const float4*)(ln_g + c0 + 4);
                *(float4*)(ov)     = *(const float4*)(ln_b + c0);
                *(float4*)(ov + 4) = *(const float4*)(ln_b + c0 + 4);
                #pragma unroll
                for (int j = 0; j < 8; j++) {
                    float t = fmaf(l0_c, wv[j], bv[j]);
                    t = fmaf((t - l0_mu) * l0_r, gv[j], ov[j]);
                    y[j] = (t > 0.f) ? t : expm1f(t);
                }
            } else {
                float v[8];
                *(float4*)(v)     = *(const float4*)(pA + c0);
                *(float4*)(v + 4) = *(const float4*)(pA + c0 + 4);
                #pragma unroll
                for (int j = 0; j < 8; j++) {
                    float t = fmaf(v[j], g_scale[c0 + j], g_shift[c0 + j]);
                    y[j] = (t > 0.f) ? t : expm1f(t);
                }
            }
            #pragma unroll
            for (int j = 0; j < 8; j++) {
                __nv_bfloat16 h = __float2bfloat16(y[j]);
                hi[j] = h; lo[j] = __float2bfloat16(y[j] - __bfloat162float(h));
            }
        } else {
            #pragma unroll
            for (int j = 0; j < 8; j++) { hi[j] = __float2bfloat16(0.f); lo[j] = hi[j]; }
        }
        int soA = arow * ASTRIDE + aq * 8;
        *(float4*)&sAh[soA] = *(float4*)&hi[0];
        *(float4*)&sAl[soA] = *(float4*)&lo[0];

        // ---- B: pre-split bf16 weights, 16 elems per thread
        int ko = brow * 32 + kc * 4 + bhalf * 2;
        int soB = brow * ASTRIDE + bhalf * 16;
        *(float4*)&sBh[soB]     = ((const float4*)Bh)[ko];
        *(float4*)&sBh[soB + 8] = ((const float4*)Bh)[ko + 1];
        *(float4*)&sBl[soB]     = ((const float4*)Bl)[ko];
        *(float4*)&sBl[soB + 8] = ((const float4*)Bl)[ko + 1];
        __syncthreads();

        // ---- compute
        #pragma unroll
        for (int k16 = 0; k16 < 2; k16++) {
            int kb = k16 * 32;  // byte offset of 16-bf16 block
            uint32_t ah[2][4], al[2][4];
            #pragma unroll
            for (int mt = 0; mt < 2; mt++) {
                int r = wm + mt * 16 + g;
                int o = r * (ASTRIDE * 2) + kb + tg * 4;
                ah[mt][0] = *(const uint32_t*)((const char*)sAh + o);
                ah[mt][1] = *(const uint32_t*)((const char*)sAh + o + 8 * ASTRIDE * 2);
                ah[mt][2] = *(const uint32_t*)((const char*)sAh + o + 16);
                ah[mt][3] = *(const uint32_t*)((const char*)sAh + o + 8 * ASTRIDE * 2 + 16);
                al[mt][0] = *(const uint32_t*)((const char*)sAl + o);
                al[mt][1] = *(const uint32_t*)((const char*)sAl + o + 8 * ASTRIDE * 2);
                al[mt][2] = *(const uint32_t*)((const char*)sAl + o + 16);
                al[mt][3] = *(const uint32_t*)((const char*)sAl + o + 8 * ASTRIDE * 2 + 16);
            }
            #pragma unroll
            for (int nt = 0; nt < 8; nt++) {
                int rb = wn + nt * 8 + g;
                int o = rb * (ASTRIDE * 2) + kb + tg * 4;
                uint32_t bh[2], bl[2];
                bh[0] = *(const uint32_t*)((const char*)sBh + o);
                bh[1] = *(const uint32_t*)((const char*)sBh + o + 16);
                bl[0] = *(const uint32_t*)((const char*)sBl + o);
                bl[1] = *(const uint32_t*)((const char*)sBl + o + 16);
                #pragma unroll
                for (int mt = 0; mt < 2; mt++) {
                    mma16816(c[mt][nt], ah[mt], bh);
                    mma16816(c[mt][nt], ah[mt], bl);
                    mma16816(c[mt][nt], al[mt], bh);
                }
            }
        }
        __syncthreads();
    }

    // ---- epilogue: fp32 out
    #pragma unroll
    for (int mt = 0; mt < 2; mt++) {
        int r0 = bm + wm + mt * 16 + g;
        #pragma unroll
        for (int nt = 0; nt < 8; nt++) {
            int col = wn + nt * 8 + tg * 2;
            if (r0 < N_NODES)
                *(float2*)&g_xw[(size_t)r0 * H + col] = make_float2(c[mt][nt][0], c[mt][nt][1]);
            if (r0 + 8 < N_NODES)
                *(float2*)&g_xw[(size_t)(r0 + 8) * H + col] = make_float2(c[mt][nt][2], c[mt][nt][3]);
        }
    }
}

// ---------------- zero BN accumulators + node counter ----------------
__global__ void k_zero_stats() {
    int t = threadIdx.x;
    g_sum[t] = 0.f;
    g_sumsq[t] = 0.f;
    if (t == 0) g_ctr = 0;
}

// ---------------- CSR aggregation, dynamic load balance, 4-edge unroll -------
__device__ __forceinline__ void f8_fma(float4& a0, float4& a1, const float4* r, int lane, float cf) {
    float4 b0 = r[lane];
    float4 b1 = r[32 + lane];
    a0.x = fmaf(cf, b0.x, a0.x); a0.y = fmaf(cf, b0.y, a0.y);
    a0.z = fmaf(cf, b0.z, a0.z); a0.w = fmaf(cf, b0.w, a0.w);
    a1.x = fmaf(cf, b1.x, a1.x); a1.y = fmaf(cf, b1.y, a1.y);
    a1.z = fmaf(cf, b1.z, a1.z); a1.w = fmaf(cf, b1.w, a1.w);
}

__global__ __launch_bounds__(256) void k_aggregate() {
    __shared__ float s_sum[H];
    __shared__ float s_sq[H];
    int tid = threadIdx.x, lane = tid & 31;
    s_sum[tid] = 0.f;
    s_sq[tid] = 0.f;
    __syncthreads();

    for (;;) {
        int node;
        if (lane == 0) node = atomicAdd(&g_ctr, 1);
        node = __shfl_sync(0xffffffffu, node, 0);
        if (node >= N_NODES) break;

        float dn = g_dinv[node];
        const float4* row = (const float4*)(g_xw + (size_t)node * H);
        float4 a0 = row[lane];
        float4 a1 = row[32 + lane];
        float w = dn * dn;
        float4 acc0 = make_float4(a0.x * w, a0.y * w, a0.z * w, a0.w * w);
        float4 acc1 = make_float4(a1.x * w, a1.y * w, a1.z * w, a1.w * w);

        int beg = g_off[node], end = g_off[node + 1];
        int j = beg;
        for (; j + 3 < end; j += 4) {
            int s0 = g_csrc[j], s1 = g_csrc[j + 1], s2 = g_csrc[j + 2], s3 = g_csrc[j + 3];
            float cf0 = g_dinv[s0] * dn, cf1 = g_dinv[s1] * dn;
            float cf2 = g_dinv[s2] * dn, cf3 = g_dinv[s3] * dn;
            const float4* r0 = (const float4*)(g_xw + (size_t)s0 * H);
            const float4* r1 = (const float4*)(g_xw + (size_t)s1 * H);
            const float4* r2 = (const float4*)(g_xw + (size_t)s2 * H);
            const float4* r3 = (const float4*)(g_xw + (size_t)s3 * H);
            float4 b0 = r0[lane], b1 = r0[32 + lane];
            float4 b2 = r1[lane], b3 = r1[32 + lane];
            float4 b4 = r2[lane], b5 = r2[32 + lane];
            float4 b6 = r3[lane], b7 = r3[32 + lane];
            acc0.x = fmaf(cf0, b0.x, acc0.x); acc0.y = fmaf(cf0, b0.y, acc0.y);
            acc0.z = fmaf(cf0, b0.z, acc0.z); acc0.w = fmaf(cf0, b0.w, acc0.w);
            acc1.x = fmaf(cf0, b1.x, acc1.x); acc1.y = fmaf(cf0, b1.y, acc1.y);
            acc1.z = fmaf(cf0, b1.z, acc1.z); acc1.w = fmaf(cf0, b1.w, acc1.w);
            acc0.x = fmaf(cf1, b2.x, acc0.x); acc0.y = fmaf(cf1, b2.y, acc0.y);
            acc0.z = fmaf(cf1, b2.z, acc0.z); acc0.w = fmaf(cf1, b2.w, acc0.w);
            acc1.x = fmaf(cf1, b3.x, acc1.x); acc1.y = fmaf(cf1, b3.y, acc1.y);
            acc1.z = fmaf(cf1, b3.z, acc1.z); acc1.w = fmaf(cf1, b3.w, acc1.w);
            acc0.x = fmaf(cf2, b4.x, acc0.x); acc0.y = fmaf(cf2, b4.y, acc0.y);
            acc0.z = fmaf(cf2, b4.z, acc0.z); acc0.w = fmaf(cf2, b4.w, acc0.w);
            acc1.x = fmaf(cf2, b5.x, acc1.x); acc1.y = fmaf(cf2, b5.y, acc1.y);
            acc1.z = fmaf(cf2, b5.z, acc1.z); acc1.w = fmaf(cf2, b5.w, acc1.w);
            acc0.x = fmaf(cf3, b6.x, acc0.x); acc0.y = fmaf(cf3, b6.y, acc0.y);
            acc0.z = fmaf(cf3, b6.z, acc0.z); acc0.w = fmaf(cf3, b6.w, acc0.w);
            acc1.x = fmaf(cf3, b7.x, acc1.x); acc1.y = fmaf(cf3, b7.y, acc1.y);
            acc1.z = fmaf(cf3, b7.z, acc1.z); acc1.w = fmaf(cf3, b7.w, acc1.w);
        }
        for (; j < end; j++) {
            int s0 = g_csrc[j];
            f8_fma(acc0, acc1, (const float4*)(g_xw + (size_t)s0 * H), lane, g_dinv[s0] * dn);
        }

        float4* out = (float4*)(g_x + (size_t)node * H);
        out[lane] = acc0;
        out[32 + lane] = acc1;

        int c0 = lane * 4, c1 = 128 + lane * 4;
        atomicAdd(&s_sum[c0 + 0], acc0.x); atomicAdd(&s_sq[c0 + 0], acc0.x * acc0.x);
        atomicAdd(&s_sum[c0 + 1], acc0.y); atomicAdd(&s_sq[c0 + 1], acc0.y * acc0.y);
        atomicAdd(&s_sum[c0 + 2], acc0.z); atomicAdd(&s_sq[c0 + 2], acc0.z * acc0.z);
        atomicAdd(&s_sum[c0 + 3], acc0.w); atomicAdd(&s_sq[c0 + 3], acc0.w * acc0.w);
        atomicAdd(&s_sum[c1 + 0], acc1.x); atomicAdd(&s_sq[c1 + 0], acc1.x * acc1.x);
        atomicAdd(&s_sum[c1 + 1], acc1.y); atomicAdd(&s_sq[c1 + 1], acc1.y * acc1.y);
        atomicAdd(&s_sum[c1 + 2], acc1.z); atomicAdd(&s_sq[c1 + 2], acc1.z * acc1.z);
        atomicAdd(&s_sum[c1 + 3], acc1.w); atomicAdd(&s_sq[c1 + 3], acc1.w * acc1.w);
    }

    __syncthreads();
    atomicAdd(&g_sum[tid], s_sum[tid]);
    atomicAdd(&g_sumsq[tid], s_sq[tid]);
}

// ---------------- BN finalize ----------------
__global__ void k_bn_finalize(const float* __restrict__ gamma,
                              const float* __restrict__ beta) {
    int t = threadIdx.x;
    float mean = g_sum[t] * (1.0f / N_NODES);
    float var = fmaxf(g_sumsq[t] * (1.0f / N_NODES) - mean * mean, 0.f);
    float r = rsqrtf(var + EPS_BN);
    float sc = r * gamma[t];
    g_scale[t] = sc;
    g_shift[t] = beta[t] - mean * sc;
}

// ---------------- head: BN3 + ELU + dot ----------------
__global__ void k_head(const float* __restrict__ w_head,
                       const float* __restrict__ b_head,
                       float* __restrict__ out) {
    int gwarp = (blockIdx.x * blockDim.x + threadIdx.x) >> 5;
    int lane = threadIdx.x & 31;
    if (gwarp >= N_NODES) return;
    const float* row = g_x + (size_t)gwarp * H + lane * 8;
    float v[8];
    *(float4*)(v)     = *(const float4*)(row);
    *(float4*)(v + 4) = *(const float4*)(row + 4);
    float s = 0.f;
    #pragma unroll
    for (int j = 0; j < 8; j++) {
        int ch = lane * 8 + j;
        float y = fmaf(v[j], g_scale[ch], g_shift[ch]);
        y = (y > 0.f) ? y : expm1f(y);
        s = fmaf(y, w_head[ch], s);
    }
    #pragma unroll
    for (int o = 16; o; o >>= 1) s += __shfl_xor_sync(0xffffffffu, s, o);
    if (lane == 0) out[gwarp] = s + b_head[0];
}

// ---------------- launch ----------------
extern "C" void kernel_launch(void* const* d_in, const int* in_sizes, int n_in,
                              void* d_out, int out_size) {
    const float* ctrl   = (const float*)d_in[0];
    const int*   eidx   = (const int*)d_in[1];
    const float* w_in   = (const float*)d_in[2];
    const float* b_in   = (const float*)d_in[3];
    const float* ln_g   = (const float*)d_in[4];
    const float* ln_b   = (const float*)d_in[5];
    const float* W[3]   = { (const float*)d_in[6],  (const float*)d_in[10], (const float*)d_in[14] };
    const float* gam[3] = { (const float*)d_in[8],  (const float*)d_in[12], (const float*)d_in[16] };
    const float* bet[3] = { (const float*)d_in[9],  (const float*)d_in[13], (const float*)d_in[17] };
    const float* w_head = (const float*)d_in[18];
    const float* b_head = (const float*)d_in[19];
    float* out = (float*)d_out;

    const int* src = eidx;
    const int* dst = eidx + E_EDGES;

    static cudaStream_t s2 = nullptr;
    static cudaEvent_t e1 = nullptr, e2 = nullptr;
    if (!s2) {
        cudaStreamCreate(&s2);
        cudaEventCreateWithFlags(&e1, cudaEventDisableTiming);
        cudaEventCreateWithFlags(&e2, cudaEventDisableTiming);
    }
    cudaFuncSetAttribute(k_gemm_mma, cudaFuncAttributeMaxDynamicSharedMemorySize, GEMM_SMEM);

    // ---- fork: CSR build on s2
    cudaEventRecord(e1, 0);
    cudaStreamWaitEvent(s2, e1, 0);
    k_zero_deg<<<(N_NODES + 255) / 256, 256, 0, s2>>>();
    k_count<<<E_EDGES / 256, 256, 0, s2>>>(dst);
    k_scan_reduce<<<NBLK_SCAN, 1024, 0, s2>>>();
    k_scan_offsets<<<1, 32, 0, s2>>>();
    k_scan_write<<<NBLK_SCAN, 1024, 0, s2>>>();
    k_fill<<<E_EDGES / 256, 256, 0, s2>>>(src, dst);
    cudaEventRecord(e2, s2);

    // ---- main stream: weight split + LN stats + layer-0 GEMM (input fused)
    __nv_bfloat16* wh;  __nv_bfloat16* wl;
    cudaGetSymbolAddress((void**)&wh, g_wth);
    cudaGetSymbolAddress((void**)&wl, g_wtl);
    for (int l = 0; l < 3; l++)
        k_wsplit<<<H, H>>>(W[l], wh + (size_t)l * H * H, wl + (size_t)l * H * H);
    k_instat<<<1, H>>>(w_in, b_in);

    int gemm_grid = (N_NODES + 127) / 128;
    for (int l = 0; l < 3; l++) {
        k_gemm_mma<<<gemm_grid, 512, GEMM_SMEM>>>(wh + (size_t)l * H * H,
                                                  wl + (size_t)l * H * H,
                                                  (l == 0) ? 0 : 2,
                                                  ctrl, w_in, b_in, ln_g, ln_b);
        if (l == 0) cudaStreamWaitEvent(0, e2, 0);   // CSR must be ready before agg
        k_zero_stats<<<1, H>>>();
        k_aggregate<<<592, 256>>>();
        k_bn_finalize<<<1, H>>>(gam[l], bet[l]);
    }

    k_head<<<N_NODES / 8, 256>>>(w_head, b_head, out);
}

// round 8
// speedup vs baseline: 1.2352x; 1.0239x over previous
#include <cuda_runtime.h>
#include <cuda_bf16.h>
#include <cstdint>
#include <math.h>

#define N_NODES 50000
#define H 256
#define E_EDGES 800000
#define EPS_LN 1e-5f
#define EPS_BN 1e-5f
#define NBLK_SCAN 49   // ceil(50000/1024)

// ---------------- scratch (device globals; no allocation allowed) -------------
__device__ float g_x[(size_t)N_NODES * H];            // aggregation output (pre-BN)
__device__ float g_xw[(size_t)N_NODES * H];           // x @ W (fp32, GEMM out / gather src)
__device__ __nv_bfloat16 g_wth[3][H * H];             // W^T hi: [n][k]
__device__ __nv_bfloat16 g_wtl[3][H * H];             // W^T lo: [n][k]
__device__ int   g_deg[N_NODES];
__device__ float g_dinv[N_NODES];
__device__ int   g_off[N_NODES + 1];
__device__ int   g_cur[N_NODES];
__device__ int   g_csrc[E_EDGES];
__device__ int   g_part[64];
__device__ int   g_ctr3[3];
__device__ float g_sumA[3][H];
__device__ float g_sumsqA[3][H];
__device__ float g_lnstat[5];   // mw, mb, vw, cwb, vb

// ---------------- degree / CSR build ----------------
__global__ void k_zero_deg() {
    int i = blockIdx.x * blockDim.x + threadIdx.x;
    if (i < N_NODES) g_deg[i] = 0;
}

__global__ void k_count(const int* __restrict__ dst) {
    int e = blockIdx.x * blockDim.x + threadIdx.x;
    if (e < E_EDGES) atomicAdd(&g_deg[dst[e]], 1);
}

__global__ void k_scan_reduce() {
    __shared__ int sw[32];
    int tid = threadIdx.x, lane = tid & 31, wid = tid >> 5;
    int i = blockIdx.x * 1024 + tid;
    int v = (i < N_NODES) ? g_deg[i] : 0;
    #pragma unroll
    for (int o = 16; o; o >>= 1) v += __shfl_xor_sync(0xffffffffu, v, o);
    if (lane == 0) sw[wid] = v;
    __syncthreads();
    if (wid == 0) {
        int t = sw[lane];
        #pragma unroll
        for (int o = 16; o; o >>= 1) t += __shfl_xor_sync(0xffffffffu, t, o);
        if (lane == 0) g_part[blockIdx.x] = t;
    }
}

__global__ void k_scan_offsets() {
    if (threadIdx.x == 0) {
        int run = 0;
        for (int b = 0; b < NBLK_SCAN; b++) {
            int t = g_part[b];
            g_part[b] = run;
            run += t;
        }
        g_off[N_NODES] = run;
    }
}

__global__ void k_scan_write() {
    __shared__ int sw[32];
    int tid = threadIdx.x, lane = tid & 31, wid = tid >> 5;
    int i = blockIdx.x * 1024 + tid;
    int v = (i < N_NODES) ? g_deg[i] : 0;
    int x = v;
    #pragma unroll
    for (int o = 1; o < 32; o <<= 1) {
        int t = __shfl_up_sync(0xffffffffu, x, o);
        if (lane >= o) x += t;
    }
    if (lane == 31) sw[wid] = x;
    __syncthreads();
    if (wid == 0) {
        int y = sw[lane];
        #pragma unroll
        for (int o = 1; o < 32; o <<= 1) {
            int t = __shfl_up_sync(0xffffffffu, y, o);
            if (lane >= o) y += t;
        }
        sw[lane] = y;
    }
    __syncthreads();
    if (i < N_NODES) {
        int excl = x - v + (wid ? sw[wid - 1] : 0) + g_part[blockIdx.x];
        g_off[i] = excl;
        g_cur[i] = excl;
        g_dinv[i] = rsqrtf((float)v + 1.0f);
    }
}

__global__ void k_fill(const int* __restrict__ src, const int* __restrict__ dst) {
    int e = blockIdx.x * blockDim.x + threadIdx.x;
    if (e < E_EDGES) {
        int d = dst[e];
        int pos = atomicAdd(&g_cur[d], 1);
        g_csrc[pos] = src[e];
    }
}

// ---------------- W^T split (fp32 -> bf16 hi/lo), [n][k] layout --------------
__global__ void k_wsplit(const float* __restrict__ W,
                         __nv_bfloat16* __restrict__ hi, __nv_bfloat16* __restrict__ lo) {
    int n = blockIdx.x, k = threadIdx.x;
    float w = W[k * H + n];
    __nv_bfloat16 h = __float2bfloat16(w);
    hi[n * H + k] = h;
    lo[n * H + k] = __float2bfloat16(w - __bfloat162float(h));
}

// ---------------- input LN stats + zero all per-layer accumulators -----------
__global__ void k_instat(const float* __restrict__ w_in, const float* __restrict__ b_in) {
    __shared__ float red[5][8];
    int t = threadIdx.x, lane = t & 31, wid = t >> 5;
    // zero per-layer BN accumulators + counters
    #pragma unroll
    for (int l = 0; l < 3; l++) {
        g_sumA[l][t] = 0.f;
        g_sumsqA[l][t] = 0.f;
    }
    if (t < 3) g_ctr3[t] = 0;

    float w = w_in[t], b = b_in[t];
    float s[5] = { w, b, w * w, w * b, b * b };
    #pragma unroll
    for (int o = 16; o; o >>= 1)
        #pragma unroll
        for (int i = 0; i < 5; i++) s[i] += __shfl_xor_sync(0xffffffffu, s[i], o);
    if (lane == 0)
        #pragma unroll
        for (int i = 0; i < 5; i++) red[i][wid] = s[i];
    __syncthreads();
    if (t == 0) {
        float a[5];
        #pragma unroll
        for (int i = 0; i < 5; i++) {
            float acc = 0.f;
            for (int j = 0; j < 8; j++) acc += red[i][j];
            a[i] = acc * (1.0f / H);
        }
        g_lnstat[0] = a[0];
        g_lnstat[1] = a[1];
        g_lnstat[2] = a[2] - a[0] * a[0];
        g_lnstat[3] = a[3] - a[0] * a[1];
        g_lnstat[4] = a[4] - a[1] * a[1];
    }
}

// ---------------- mma.sync bf16 GEMM, double-buffered, BN fused --------------
// mode 0: A = elu(LN(ctrl*w_in+b_in)) closed-form (layer 0)
// mode 2: A = elu(bn(g_x)) with scale/shift computed inline from raw sums
#define ASTRIDE 40   // bf16 elems per smem row (80 B)
#define SA_ELEMS (128 * ASTRIDE)
#define SB_ELEMS (256 * ASTRIDE)
#define BUF_ELEMS (2 * SA_ELEMS + 2 * SB_ELEMS)
#define GEMM_SMEM (2 * BUF_ELEMS * 2)

__device__ __forceinline__ void mma16816(float* c, const uint32_t* a, const uint32_t* b) {
    asm volatile("mma.sync.aligned.m16n8k16.row.col.f32.bf16.bf16.f32 "
                 "{%0,%1,%2,%3}, {%4,%5,%6,%7}, {%8,%9}, {%0,%1,%2,%3};"
                 : "+f"(c[0]), "+f"(c[1]), "+f"(c[2]), "+f"(c[3])
                 : "r"(a[0]), "r"(a[1]), "r"(a[2]), "r"(a[3]), "r"(b[0]), "r"(b[1]));
}

__global__ __launch_bounds__(512, 1) void k_gemm_mma(const __nv_bfloat16* __restrict__ Bh,
                                                     const __nv_bfloat16* __restrict__ Bl,
                                                     int mode,
                                                     const float* __restrict__ ctrl,
                                                     const float* __restrict__ w_in,
                                                     const float* __restrict__ b_in,
                                                     const float* __restrict__ ln_g,
                                                     const float* __restrict__ ln_b,
                                                     const float* __restrict__ sumv,
                                                     const float* __restrict__ sumsqv,
                                                     const float* __restrict__ gamma,
                                                     const float* __restrict__ beta) {
    extern __shared__ __nv_bfloat16 smem[];

    int tid = threadIdx.x, wid = tid >> 5, lane = tid & 31;
    int g = lane >> 2, tg = lane & 3;
    int bm = blockIdx.x * 128;
    int wm = (wid & 3) * 32, wn = (wid >> 2) * 64;

    float c[2][8][4] = {};

    // A mapping: 128 rows x 32 k, 8 fp32 per thread
    int arow = tid >> 2, aq = tid & 3;
    int gr = bm + arow;
    bool a_ok = (gr < N_NODES);
    const float* pA = g_x + (size_t)(a_ok ? gr : 0) * H;
    // layer-0 closed-form LN per row
    float l0_c = 0.f, l0_mu = 0.f, l0_r = 0.f;
    if (mode == 0 && a_ok) {
        l0_c = ctrl[gr];
        l0_mu = fmaf(l0_c, g_lnstat[0], g_lnstat[1]);
        float var = fmaf(l0_c * l0_c, g_lnstat[2],
                    fmaf(2.0f * l0_c, g_lnstat[3], g_lnstat[4]));
        l0_r = rsqrtf(fmaxf(var, 0.f) + EPS_LN);
    }
    // B mapping: 256 rows x 32 k, 16 bf16 per thread
    int brow = tid >> 1, bhalf = tid & 1;
    int soA = arow * ASTRIDE + aq * 8;
    int soB = brow * ASTRIDE + bhalf * 16;

    float aPre[8];
    float4 bPre[4];

    // ---- helpers as macros over locals
    #define LOAD_NEXT(kcn) do {                                                 \
        int _c0 = (kcn) * 32 + aq * 8;                                          \
        if (mode != 0) {                                                        \
            if (a_ok) {                                                         \
                *(float4*)(aPre)     = *(const float4*)(pA + _c0);              \
                *(float4*)(aPre + 4) = *(const float4*)(pA + _c0 + 4);          \
            }                                                                   \
        }                                                                       \
        int _ko = brow * 32 + (kcn) * 4 + bhalf * 2;                            \
        bPre[0] = ((const float4*)Bh)[_ko];                                     \
        bPre[1] = ((const float4*)Bh)[_ko + 1];                                 \
        bPre[2] = ((const float4*)Bl)[_ko];                                     \
        bPre[3] = ((const float4*)Bl)[_ko + 1];                                 \
    } while (0)

    #define XFORM_STORE(kcn, bufi) do {                                         \
        __nv_bfloat16* _base = smem + (bufi) * BUF_ELEMS;                       \
        __nv_bfloat16* _sAh = _base;                                            \
        __nv_bfloat16* _sAl = _base + SA_ELEMS;                                 \
        __nv_bfloat16* _sBh = _base + 2 * SA_ELEMS;                             \
        __nv_bfloat16* _sBl = _base + 2 * SA_ELEMS + SB_ELEMS;                  \
        int _c0 = (kcn) * 32 + aq * 8;                                          \
        __nv_bfloat16 _hi[8], _lo[8];                                           \
        if (a_ok) {                                                             \
            float _y[8];                                                        \
            if (mode == 0) {                                                    \
                float _wv[8], _bv[8], _gv[8], _ov[8];                           \
                *(float4*)(_wv)     = *(const float4*)(w_in + _c0);             \
                *(float4*)(_wv + 4) = *(const float4*)(w_in + _c0 + 4);         \
                *(float4*)(_bv)     = *(const float4*)(b_in + _c0);             \
                *(float4*)(_bv + 4) = *(const float4*)(b_in + _c0 + 4);         \
                *(float4*)(_gv)     = *(const float4*)(ln_g + _c0);             \
                *(float4*)(_gv + 4) = *(const float4*)(ln_g + _c0 + 4);         \
                *(float4*)(_ov)     = *(const float4*)(ln_b + _c0);             \
                *(float4*)(_ov + 4) = *(const float4*)(ln_b + _c0 + 4);         \
                _Pragma("unroll")                                               \
                for (int _j = 0; _j < 8; _j++) {                                \
                    float _t = fmaf(l0_c, _wv[_j], _bv[_j]);                    \
                    _t = fmaf((_t - l0_mu) * l0_r, _gv[_j], _ov[_j]);           \
                    _y[_j] = (_t > 0.f) ? _t : expm1f(_t);                      \
                }                                                               \
            } else {                                                            \
                float _sv[8], _qv[8], _gv[8], _ov[8];                           \
                *(float4*)(_sv)     = *(const float4*)(sumv + _c0);             \
                *(float4*)(_sv + 4) = *(const float4*)(sumv + _c0 + 4);         \
                *(float4*)(_qv)     = *(const float4*)(sumsqv + _c0);           \
                *(float4*)(_qv + 4) = *(const float4*)(sumsqv + _c0 + 4);       \
                *(float4*)(_gv)     = *(const float4*)(gamma + _c0);            \
                *(float4*)(_gv + 4) = *(const float4*)(gamma + _c0 + 4);        \
                *(float4*)(_ov)     = *(const float4*)(beta + _c0);             \
                *(float4*)(_ov + 4) = *(const float4*)(beta + _c0 + 4);         \
                _Pragma("unroll")                                               \
                for (int _j = 0; _j < 8; _j++) {                                \
                    float _mean = _sv[_j] * (1.0f / N_NODES);                   \
                    float _var = fmaxf(_qv[_j] * (1.0f / N_NODES) - _mean * _mean, 0.f); \
                    float _r = rsqrtf(_var + EPS_BN);                           \
                    float _sc = _r * _gv[_j];                                   \
                    float _sh = _ov[_j] - _mean * _sc;                          \
                    float _t = fmaf(aPre[_j], _sc, _sh);                        \
                    _y[_j] = (_t > 0.f) ? _t : expm1f(_t);                      \
                }                                                               \
            }                                                                   \
            _Pragma("unroll")                                                   \
            for (int _j = 0; _j < 8; _j++) {                                    \
                __nv_bfloat16 _h = __float2bfloat16(_y[_j]);                    \
                _hi[_j] = _h;                                                   \
                _lo[_j] = __float2bfloat16(_y[_j] - __bfloat162float(_h));      \
            }                                                                   \
        } else {                                                                \
            _Pragma("unroll")                                                   \
            for (int _j = 0; _j < 8; _j++) { _hi[_j] = __float2bfloat16(0.f); _lo[_j] = _hi[_j]; } \
        }                                                                       \
        *(float4*)&_sAh[soA] = *(float4*)&_hi[0];                               \
        *(float4*)&_sAl[soA] = *(float4*)&_lo[0];                               \
        *(float4*)&_sBh[soB]     = bPre[0];                                     \
        *(float4*)&_sBh[soB + 8] = bPre[1];                                     \
        *(float4*)&_sBl[soB]     = bPre[2];                                     \
        *(float4*)&_sBl[soB + 8] = bPre[3];                                     \
    } while (0)

    // prologue: chunk 0
    LOAD_NEXT(0);
    XFORM_STORE(0, 0);
    __syncthreads();

    for (int kc = 0; kc < 8; kc++) {
        int cur = kc & 1;
        if (kc < 7) LOAD_NEXT(kc + 1);

        // ---- compute from buffer `cur`
        const char* bAh = (const char*)(smem + cur * BUF_ELEMS);
        const char* bAl = bAh + SA_ELEMS * 2;
        const char* bBh = bAh + 2 * SA_ELEMS * 2;
        const char* bBl = bAh + (2 * SA_ELEMS + SB_ELEMS) * 2;
        #pragma unroll
        for (int k16 = 0; k16 < 2; k16++) {
            int kb = k16 * 32;
            uint32_t ah[2][4], al[2][4];
            #pragma unroll
            for (int mt = 0; mt < 2; mt++) {
                int r = wm + mt * 16 + g;
                int o = r * (ASTRIDE * 2) + kb + tg * 4;
                ah[mt][0] = *(const uint32_t*)(bAh + o);
                ah[mt][1] = *(const uint32_t*)(bAh + o + 8 * ASTRIDE * 2);
                ah[mt][2] = *(const uint32_t*)(bAh + o + 16);
                ah[mt][3] = *(const uint32_t*)(bAh + o + 8 * ASTRIDE * 2 + 16);
                al[mt][0] = *(const uint32_t*)(bAl + o);
                al[mt][1] = *(const uint32_t*)(bAl + o + 8 * ASTRIDE * 2);
                al[mt][2] = *(const uint32_t*)(bAl + o + 16);
                al[mt][3] = *(const uint32_t*)(bAl + o + 8 * ASTRIDE * 2 + 16);
            }
            #pragma unroll
            for (int nt = 0; nt < 8; nt++) {
                int rb = wn + nt * 8 + g;
                int o = rb * (ASTRIDE * 2) + kb + tg * 4;
                uint32_t bh[2], bl[2];
                bh[0] = *(const uint32_t*)(bBh + o);
                bh[1] = *(const uint32_t*)(bBh + o + 16);
                bl[0] = *(const uint32_t*)(bBl + o);
                bl[1] = *(const uint32_t*)(bBl + o + 16);
                #pragma unroll
                for (int mt = 0; mt < 2; mt++) {
                    mma16816(c[mt][nt], ah[mt], bh);
                    mma16816(c[mt][nt], ah[mt], bl);
                    mma16816(c[mt][nt], al[mt], bh);
                }
            }
        }

        if (kc < 7) XFORM_STORE(kc + 1, cur ^ 1);
        __syncthreads();
    }

    // ---- epilogue: fp32 out
    #pragma unroll
    for (int mt = 0; mt < 2; mt++) {
        int r0 = bm + wm + mt * 16 + g;
        #pragma unroll
        for (int nt = 0; nt < 8; nt++) {
            int col = wn + nt * 8 + tg * 2;
            if (r0 < N_NODES)
                *(float2*)&g_xw[(size_t)r0 * H + col] = make_float2(c[mt][nt][0], c[mt][nt][1]);
            if (r0 + 8 < N_NODES)
                *(float2*)&g_xw[(size_t)(r0 + 8) * H + col] = make_float2(c[mt][nt][2], c[mt][nt][3]);
        }
    }
    #undef LOAD_NEXT
    #undef XFORM_STORE
}

// ---------------- CSR aggregation, dynamic load balance, 4-edge unroll -------
__device__ __forceinline__ void f8_fma(float4& a0, float4& a1, const float4* r, int lane, float cf) {
    float4 b0 = r[lane];
    float4 b1 = r[32 + lane];
    a0.x = fmaf(cf, b0.x, a0.x); a0.y = fmaf(cf, b0.y, a0.y);
    a0.z = fmaf(cf, b0.z, a0.z); a0.w = fmaf(cf, b0.w, a0.w);
    a1.x = fmaf(cf, b1.x, a1.x); a1.y = fmaf(cf, b1.y, a1.y);
    a1.z = fmaf(cf, b1.z, a1.z); a1.w = fmaf(cf, b1.w, a1.w);
}

__global__ __launch_bounds__(256) void k_aggregate(int layer) {
    __shared__ float s_sum[H];
    __shared__ float s_sq[H];
    int tid = threadIdx.x, lane = tid & 31;
    s_sum[tid] = 0.f;
    s_sq[tid] = 0.f;
    __syncthreads();

    int* ctr = &g_ctr3[layer];
    for (;;) {
        int node;
        if (lane == 0) node = atomicAdd(ctr, 1);
        node = __shfl_sync(0xffffffffu, node, 0);
        if (node >= N_NODES) break;

        float dn = g_dinv[node];
        const float4* row = (const float4*)(g_xw + (size_t)node * H);
        float4 a0 = row[lane];
        float4 a1 = row[32 + lane];
        float w = dn * dn;
        float4 acc0 = make_float4(a0.x * w, a0.y * w, a0.z * w, a0.w * w);
        float4 acc1 = make_float4(a1.x * w, a1.y * w, a1.z * w, a1.w * w);

        int beg = g_off[node], end = g_off[node + 1];
        int j = beg;
        for (; j + 3 < end; j += 4) {
            int s0 = g_csrc[j], s1 = g_csrc[j + 1], s2 = g_csrc[j + 2], s3 = g_csrc[j + 3];
            float cf0 = g_dinv[s0] * dn, cf1 = g_dinv[s1] * dn;
            float cf2 = g_dinv[s2] * dn, cf3 = g_dinv[s3] * dn;
            const float4* r0 = (const float4*)(g_xw + (size_t)s0 * H);
            const float4* r1 = (const float4*)(g_xw + (size_t)s1 * H);
            const float4* r2 = (const float4*)(g_xw + (size_t)s2 * H);
            const float4* r3 = (const float4*)(g_xw + (size_t)s3 * H);
            float4 b0 = r0[lane], b1 = r0[32 + lane];
            float4 b2 = r1[lane], b3 = r1[32 + lane];
            float4 b4 = r2[lane], b5 = r2[32 + lane];
            float4 b6 = r3[lane], b7 = r3[32 + lane];
            acc0.x = fmaf(cf0, b0.x, acc0.x); acc0.y = fmaf(cf0, b0.y, acc0.y);
            acc0.z = fmaf(cf0, b0.z, acc0.z); acc0.w = fmaf(cf0, b0.w, acc0.w);
            acc1.x = fmaf(cf0, b1.x, acc1.x); acc1.y = fmaf(cf0, b1.y, acc1.y);
            acc1.z = fmaf(cf0, b1.z, acc1.z); acc1.w = fmaf(cf0, b1.w, acc1.w);
            acc0.x = fmaf(cf1, b2.x, acc0.x); acc0.y = fmaf(cf1, b2.y, acc0.y);
            acc0.z = fmaf(cf1, b2.z, acc0.z); acc0.w = fmaf(cf1, b2.w, acc0.w);
            acc1.x = fmaf(cf1, b3.x, acc1.x); acc1.y = fmaf(cf1, b3.y, acc1.y);
            acc1.z = fmaf(cf1, b3.z, acc1.z); acc1.w = fmaf(cf1, b3.w, acc1.w);
            acc0.x = fmaf(cf2, b4.x, acc0.x); acc0.y = fmaf(cf2, b4.y, acc0.y);
            acc0.z = fmaf(cf2, b4.z, acc0.z); acc0.w = fmaf(cf2, b4.w, acc0.w);
            acc1.x = fmaf(cf2, b5.x, acc1.x); acc1.y = fmaf(cf2, b5.y, acc1.y);
            acc1.z = fmaf(cf2, b5.z, acc1.z); acc1.w = fmaf(cf2, b5.w, acc1.w);
            acc0.x = fmaf(cf3, b6.x, acc0.x); acc0.y = fmaf(cf3, b6.y, acc0.y);
            acc0.z = fmaf(cf3, b6.z, acc0.z); acc0.w = fmaf(cf3, b6.w, acc0.w);
            acc1.x = fmaf(cf3, b7.x, acc1.x); acc1.y = fmaf(cf3, b7.y, acc1.y);
            acc1.z = fmaf(cf3, b7.z, acc1.z); acc1.w = fmaf(cf3, b7.w, acc1.w);
        }
        for (; j < end; j++) {
            int s0 = g_csrc[j];
            f8_fma(acc0, acc1, (const float4*)(g_xw + (size_t)s0 * H), lane, g_dinv[s0] * dn);
        }

        float4* out = (float4*)(g_x + (size_t)node * H);
        out[lane] = acc0;
        out[32 + lane] = acc1;

        int c0 = lane * 4, c1 = 128 + lane * 4;
        atomicAdd(&s_sum[c0 + 0], acc0.x); atomicAdd(&s_sq[c0 + 0], acc0.x * acc0.x);
        atomicAdd(&s_sum[c0 + 1], acc0.y); atomicAdd(&s_sq[c0 + 1], acc0.y * acc0.y);
        atomicAdd(&s_sum[c0 + 2], acc0.z); atomicAdd(&s_sq[c0 + 2], acc0.z * acc0.z);
        atomicAdd(&s_sum[c0 + 3], acc0.w); atomicAdd(&s_sq[c0 + 3], acc0.w * acc0.w);
        atomicAdd(&s_sum[c1 + 0], acc1.x); atomicAdd(&s_sq[c1 + 0], acc1.x * acc1.x);
        atomicAdd(&s_sum[c1 + 1], acc1.y); atomicAdd(&s_sq[c1 + 1], acc1.y * acc1.y);
        atomicAdd(&s_sum[c1 + 2], acc1.z); atomicAdd(&s_sq[c1 + 2], acc1.z * acc1.z);
        atomicAdd(&s_sum[c1 + 3], acc1.w); atomicAdd(&s_sq[c1 + 3], acc1.w * acc1.w);
    }

    __syncthreads();
    atomicAdd(&g_sumA[layer][tid], s_sum[tid]);
    atomicAdd(&g_sumsqA[layer][tid], s_sq[tid]);
}

// ---------------- head: BN3 (inline finalize) + ELU + dot ----------------
__global__ void k_head(const float* __restrict__ w_head,
                       const float* __restrict__ b_head,
                       const float* __restrict__ gamma,
                       const float* __restrict__ beta,
                       float* __restrict__ out) {
    int gwarp = (blockIdx.x * blockDim.x + threadIdx.x) >> 5;
    int lane = threadIdx.x & 31;
    if (gwarp >= N_NODES) return;
    const float* row = g_x + (size_t)gwarp * H + lane * 8;
    float v[8];
    *(float4*)(v)     = *(const float4*)(row);
    *(float4*)(v + 4) = *(const float4*)(row + 4);
    float s = 0.f;
    #pragma unroll
    for (int j = 0; j < 8; j++) {
        int ch = lane * 8 + j;
        float mean = g_sumA[2][ch] * (1.0f / N_NODES);
        float var = fmaxf(g_sumsqA[2][ch] * (1.0f / N_NODES) - mean * mean, 0.f);
        float r = rsqrtf(var + EPS_BN);
        float sc = r * gamma[ch];
        float sh = beta[ch] - mean * sc;
        float y = fmaf(v[j], sc, sh);
        y = (y > 0.f) ? y : expm1f(y);
        s = fmaf(y, w_head[ch], s);
    }
    #pragma unroll
    for (int o = 16; o; o >>= 1) s += __shfl_xor_sync(0xffffffffu, s, o);
    if (lane == 0) out[gwarp] = s + b_head[0];
}

// ---------------- launch ----------------
extern "C" void kernel_launch(void* const* d_in, const int* in_sizes, int n_in,
                              void* d_out, int out_size) {
    const float* ctrl   = (const float*)d_in[0];
    const int*   eidx   = (const int*)d_in[1];
    const float* w_in   = (const float*)d_in[2];
    const float* b_in   = (const float*)d_in[3];
    const float* ln_g   = (const float*)d_in[4];
    const float* ln_b   = (const float*)d_in[5];
    const float* W[3]   = { (const float*)d_in[6],  (const float*)d_in[10], (const float*)d_in[14] };
    const float* gam[3] = { (const float*)d_in[8],  (const float*)d_in[12], (const float*)d_in[16] };
    const float* bet[3] = { (const float*)d_in[9],  (const float*)d_in[13], (const float*)d_in[17] };
    const float* w_head = (const float*)d_in[18];
    const float* b_head = (const float*)d_in[19];
    float* out = (float*)d_out;

    const int* src = eidx;
    const int* dst = eidx + E_EDGES;

    static cudaStream_t s2 = nullptr;
    static cudaEvent_t e1 = nullptr, e2 = nullptr;
    if (!s2) {
        cudaStreamCreate(&s2);
        cudaEventCreateWithFlags(&e1, cudaEventDisableTiming);
        cudaEventCreateWithFlags(&e2, cudaEventDisableTiming);
    }
    cudaFuncSetAttribute(k_gemm_mma, cudaFuncAttributeMaxDynamicSharedMemorySize, GEMM_SMEM);

    __nv_bfloat16* wh;  __nv_bfloat16* wl;
    cudaGetSymbolAddress((void**)&wh, g_wth);
    cudaGetSymbolAddress((void**)&wl, g_wtl);
    float* sumP;  float* sumsqP;
    cudaGetSymbolAddress((void**)&sumP, g_sumA);
    cudaGetSymbolAddress((void**)&sumsqP, g_sumsqA);

    // ---- fork: CSR build + late weight splits on s2
    cudaEventRecord(e1, 0);
    cudaStreamWaitEvent(s2, e1, 0);
    k_zero_deg<<<(N_NODES + 255) / 256, 256, 0, s2>>>();
    k_count<<<E_EDGES / 256, 256, 0, s2>>>(dst);
    k_scan_reduce<<<NBLK_SCAN, 1024, 0, s2>>>();
    k_scan_offsets<<<1, 32, 0, s2>>>();
    k_scan_write<<<NBLK_SCAN, 1024, 0, s2>>>();
    k_fill<<<E_EDGES / 256, 256, 0, s2>>>(src, dst);
    k_wsplit<<<H, H, 0, s2>>>(W[1], wh + (size_t)1 * H * H, wl + (size_t)1 * H * H);
    k_wsplit<<<H, H, 0, s2>>>(W[2], wh + (size_t)2 * H * H, wl + (size_t)2 * H * H);
    cudaEventRecord(e2, s2);

    // ---- main stream
    k_wsplit<<<H, H>>>(W[0], wh, wl);
    k_instat<<<1, H>>>(w_in, b_in);

    int gemm_grid = (N_NODES + 127) / 128;
    for (int l = 0; l < 3; l++) {
        k_gemm_mma<<<gemm_grid, 512, GEMM_SMEM>>>(
            wh + (size_t)l * H * H, wl + (size_t)l * H * H,
            (l == 0) ? 0 : 2, ctrl, w_in, b_in, ln_g, ln_b,
            (l > 0) ? sumP + (l - 1) * H : nullptr,
            (l > 0) ? sumsqP + (l - 1) * H : nullptr,
            (l > 0) ? gam[l - 1] : nullptr,
            (l > 0) ? bet[l - 1] : nullptr);
        if (l == 0) cudaStreamWaitEvent(0, e2, 0);   // CSR + wsplit1/2 ready
        k_aggregate<<<592, 256>>>(l);
    }

    k_head<<<N_NODES / 8, 256>>>(w_head, b_head, gam[2], bet[2], out);
}